// round 12
// baseline (speedup 1.0000x reference)
#include <cuda_runtime.h>
#include <cstdint>

// Depthwise 3x3 conv, stride 1, VALID, C=64.
// x: (16, 64, 512, 512) f32, w: (64, 3, 3) f32 -> out: (16, 64, 510, 510) f32
//
// R12: ring-buffered cp.async pipeline. 12 smem row slots used as a ring;
// TILE_H=30 output rows per block (510 = 17*30). Prologue fills the ring
// (12 commit groups); iterations 0..19 each issue ONE new row load (row
// r+12 -> slot r%12) after the row-r sync, so load issue is spread across
// the block instead of bursting at start (R8's drain tail was the residual
// DRAM idle). Consume loop is R8's proven per-row wait_group+__syncthreads
// with the rolling 3-row FFMA2 window; steady-state wait level is a
// constant wait_group<9>.

#define TILE_H 30    // 510 = 17 * 30
#define RING   12    // smem row slots
#define THREADS 128  // 128 threads * 4 cols = 512
#define SLOT_F 520   // floats per slot (512 data + 2 zero + pad)

typedef unsigned long long u64;

__device__ __forceinline__ u64 fpack2(float lo, float hi) {
    u64 d;
    asm("mov.b64 %0, {%1, %2};" : "=l"(d) : "f"(lo), "f"(hi));
    return d;
}

__device__ __forceinline__ u64 fmul2(u64 a, u64 b) {
    u64 d;
    asm("mul.rn.f32x2 %0, %1, %2;" : "=l"(d) : "l"(a), "l"(b));
    return d;
}

__device__ __forceinline__ u64 ffma2(u64 a, u64 b, u64 c) {
    u64 d;
    asm("fma.rn.f32x2 %0, %1, %2, %3;" : "=l"(d) : "l"(a), "l"(b), "l"(c));
    return d;
}

__device__ __forceinline__ void cp_async16(uint32_t smem_addr,
                                           const float* gptr) {
    asm volatile("cp.async.cg.shared.global [%0], [%1], 16;"
                 :: "r"(smem_addr), "l"(gptr));
}

__device__ __forceinline__ void cp_commit() {
    asm volatile("cp.async.commit_group;");
}

template <int N>
__device__ __forceinline__ void cp_wait() {
    asm volatile("cp.async.wait_group %0;" :: "n"(N));
}

// Wait so that row r+2's group has retired. Issued-before-wait at iter r:
// 12 (prologue) + r (in-loop rows 12..r+11). Need rows 0..r+2 done ->
// allowed pending = 9 for r <= 20, then 29-r. r is compile-time.
__device__ __forceinline__ void cp_wait_rt(int r) {
    if (r <= 20) cp_wait<9>();
    else if (r == 21) cp_wait<8>();
    else if (r == 22) cp_wait<7>();
    else if (r == 23) cp_wait<6>();
    else if (r == 24) cp_wait<5>();
    else if (r == 25) cp_wait<4>();
    else if (r == 26) cp_wait<3>();
    else if (r == 27) cp_wait<2>();
    else if (r == 28) cp_wait<1>();
    else cp_wait<0>();
}

// Build 5 overlapping f32x2 pairs from a smem row slot (uniform; cols
// 512/513 hold zeros so thread 127 needs no branch).
__device__ __forceinline__ void pairs_from_smem(const float* srow, int x0,
                                                u64 q[5]) {
    float4 a = *reinterpret_cast<const float4*>(srow + x0);
    float2 b = *reinterpret_cast<const float2*>(srow + x0 + 4);
    q[0] = fpack2(a.x, a.y);
    q[1] = fpack2(a.y, a.z);
    q[2] = fpack2(a.z, a.w);
    q[3] = fpack2(a.w, b.x);
    q[4] = fpack2(b.x, b.y);
}

__global__ void __launch_bounds__(THREADS)
dwconv3x3_kernel(const float* __restrict__ x,
                 const float* __restrict__ w,
                 float* __restrict__ out) {
    __shared__ __align__(16) float sm[RING * SLOT_F];

    const int tile = blockIdx.x;   // 0..16
    const int c    = blockIdx.y;   // 0..63
    const int n    = blockIdx.z;   // 0..15

    const int tid = threadIdx.x;
    const int x0  = tid * 4;               // first owned output column
    const bool last = (x0 == 508);         // thread 127: 2 valid outputs only

    const size_t img_off = ((size_t)(n * 64 + c)) * (512 * 512);
    const size_t out_off = ((size_t)(n * 64 + c)) * (510 * 510);
    const float* img = x + img_off;
    float* o = out + out_off;

    const int r0 = tile * TILE_H;          // first output row of this tile

    const uint32_t smem_base =
        (uint32_t)__cvta_generic_to_shared(sm) + (uint32_t)(x0 * 4);

    // Prologue: fill the ring (rows 0..11), one commit-group per row.
#pragma unroll
    for (int rr = 0; rr < RING; ++rr) {
        cp_async16(smem_base + rr * (SLOT_F * 4),
                   img + (size_t)(r0 + rr) * 512 + x0);
        cp_commit();
    }

    // Zero the 2 halo floats of each slot (cols 512/513). cp.async never
    // touches these bytes, so they stay zero across ring reuse.
    if (tid < RING) {
        *reinterpret_cast<float2*>(sm + tid * SLOT_F + 512) =
            make_float2(0.0f, 0.0f);
    }

    // Broadcast weights as (w,w) f32x2 pairs.
    const float* wc = w + c * 9;
    u64 wp[9];
#pragma unroll
    for (int i = 0; i < 9; ++i) {
        float wv = __ldg(wc + i);
        wp[i] = fpack2(wv, wv);
    }

    // Rolling 3-row window of overlapping pairs.
    u64 q[3][5];
    cp_wait<RING - 2>();      // rows 0,1 retired (groups retire in order)
    __syncthreads();
    pairs_from_smem(sm + 0 * SLOT_F, x0, q[0]);
    pairs_from_smem(sm + 1 * SLOT_F, x0, q[1]);

#pragma unroll
    for (int r = 0; r < TILE_H; ++r) {
        const int top = r % 3;
        const int mid = (r + 1) % 3;
        const int bot = (r + 2) % 3;

        cp_wait_rt(r);        // row r+2 landed
        __syncthreads();      // also fences slot r%12 reads (done at r-2)

        // Issue next row into the freed slot: row r+12 -> slot r%12.
        // Safe: that slot's previous row (r) was read at iteration r-2
        // (or in the prologue), and a __syncthreads has passed since.
        if (r < TILE_H - 10) {
            cp_async16(smem_base + (r % RING) * (SLOT_F * 4),
                       img + (size_t)(r0 + r + RING) * 512 + x0);
            cp_commit();
        }

        pairs_from_smem(sm + ((r + 2) % RING) * SLOT_F, x0, q[bot]);

        // outputs (x0, x0+1)
        u64 acc01 = fmul2(wp[0], q[top][0]);
        acc01 = ffma2(wp[1], q[top][1], acc01);
        acc01 = ffma2(wp[2], q[top][2], acc01);
        acc01 = ffma2(wp[3], q[mid][0], acc01);
        acc01 = ffma2(wp[4], q[mid][1], acc01);
        acc01 = ffma2(wp[5], q[mid][2], acc01);
        acc01 = ffma2(wp[6], q[bot][0], acc01);
        acc01 = ffma2(wp[7], q[bot][1], acc01);
        acc01 = ffma2(wp[8], q[bot][2], acc01);

        // outputs (x0+2, x0+3)
        u64 acc23 = fmul2(wp[0], q[top][2]);
        acc23 = ffma2(wp[1], q[top][3], acc23);
        acc23 = ffma2(wp[2], q[top][4], acc23);
        acc23 = ffma2(wp[3], q[mid][2], acc23);
        acc23 = ffma2(wp[4], q[mid][3], acc23);
        acc23 = ffma2(wp[5], q[mid][4], acc23);
        acc23 = ffma2(wp[6], q[bot][2], acc23);
        acc23 = ffma2(wp[7], q[bot][3], acc23);
        acc23 = ffma2(wp[8], q[bot][4], acc23);

        // Row stride 510*4 = 2040 B is 8-byte aligned -> STG.64 stores.
        float* orow = o + (size_t)(r0 + r) * 510 + x0;
        *reinterpret_cast<u64*>(orow) = acc01;
        if (!last) {
            *reinterpret_cast<u64*>(orow + 2) = acc23;
        }
    }
}

extern "C" void kernel_launch(void* const* d_in, const int* in_sizes, int n_in,
                              void* d_out, int out_size) {
    const float* x = (const float*)d_in[0];
    const float* w = (const float*)d_in[1];
    // Defensive: metadata order is (x, weight); swap if sizes say otherwise.
    if (n_in >= 2 && in_sizes[0] < in_sizes[1]) {
        const float* t = x; x = w; w = t;
    }
    float* out = (float*)d_out;

    dim3 grid(17, 64, 16); // 510/TILE_H row tiles, C, N
    dwconv3x3_kernel<<<grid, THREADS>>>(x, w, out);
}

// round 14
// speedup vs baseline: 1.0034x; 1.0034x over previous
#include <cuda_runtime.h>
#include <cstdint>

// Depthwise 3x3 conv, stride 1, VALID, C=64.
// x: (16, 64, 512, 512) f32, w: (64, 3, 3) f32 -> out: (16, 64, 510, 510) f32
//
// R13 = R8 pipeline (burst 12-row cp.async prefetch, per-row progressive
// wait, rolling 3-row FFMA2 window -- best so far at 305us / 87.3% DRAM)
// with WARP-PRIVATE smem regions: each warp's 32 lanes write their own 16B
// plus lane 31 writes the warp's 8B halo, so every lane reads only bytes
// written by its own warp. The per-row block-wide __syncthreads becomes a
// per-row __syncwarp (thread-scope cp.async pipeline pattern), removing all
// BAR.SYNC and letting warps drift/stagger their load-compute phases.
//
// Per-row per-warp region: 130 floats of data (lane l: float4 at +4l,
// halo pair at +128 = +4*32), padded to 132 for 16B alignment.
// Warp 3's halo (img cols 512/513) feeds only the unstored outputs of
// thread 127 -> always loaded from a safe dummy address (no OOB, no zero
// fill needed).

#define TILE_H 10    // 510 = 51 * 10
#define ROWS_IN (TILE_H + 2)
#define THREADS 128  // 4 warps * 32 lanes, 4 output cols per thread
#define WREG_F 132   // floats per warp region (130 data + 2 pad)
#define ROW_F (4 * WREG_F)  // floats per row slot (528)

typedef unsigned long long u64;

__device__ __forceinline__ u64 fpack2(float lo, float hi) {
    u64 d;
    asm("mov.b64 %0, {%1, %2};" : "=l"(d) : "f"(lo), "f"(hi));
    return d;
}

__device__ __forceinline__ u64 fmul2(u64 a, u64 b) {
    u64 d;
    asm("mul.rn.f32x2 %0, %1, %2;" : "=l"(d) : "l"(a), "l"(b));
    return d;
}

__device__ __forceinline__ u64 ffma2(u64 a, u64 b, u64 c) {
    u64 d;
    asm("fma.rn.f32x2 %0, %1, %2, %3;" : "=l"(d) : "l"(a), "l"(b), "l"(c));
    return d;
}

__device__ __forceinline__ void cp_async16(uint32_t smem_addr,
                                           const float* gptr) {
    asm volatile("cp.async.cg.shared.global [%0], [%1], 16;"
                 :: "r"(smem_addr), "l"(gptr));
}

__device__ __forceinline__ void cp_async8(uint32_t smem_addr,
                                          const float* gptr) {
    asm volatile("cp.async.ca.shared.global [%0], [%1], 8;"
                 :: "r"(smem_addr), "l"(gptr));
}

__device__ __forceinline__ void cp_commit() {
    asm volatile("cp.async.commit_group;");
}

template <int N>
__device__ __forceinline__ void cp_wait() {
    asm volatile("cp.async.wait_group %0;" :: "n"(N));
}

// Progressive wait; r is compile-time in the unrolled loop, branches fold.
__device__ __forceinline__ void cp_wait_rt(int r) {
    if (r == 0) cp_wait<9>();
    else if (r == 1) cp_wait<8>();
    else if (r == 2) cp_wait<7>();
    else if (r == 3) cp_wait<6>();
    else if (r == 4) cp_wait<5>();
    else if (r == 5) cp_wait<4>();
    else if (r == 6) cp_wait<3>();
    else if (r == 7) cp_wait<2>();
    else if (r == 8) cp_wait<1>();
    else cp_wait<0>();
}

// Build 5 overlapping f32x2 pairs from this lane's view of a warp region:
// float4 at +4*lane, float2 at +4*(lane+1) -- contiguous 6 floats, all
// written by this warp's own cp.asyncs.
__device__ __forceinline__ void pairs_from_region(const float* lanePtr,
                                                  u64 q[5]) {
    float4 a = *reinterpret_cast<const float4*>(lanePtr);
    float2 b = *reinterpret_cast<const float2*>(lanePtr + 4);
    q[0] = fpack2(a.x, a.y);
    q[1] = fpack2(a.y, a.z);
    q[2] = fpack2(a.z, a.w);
    q[3] = fpack2(a.w, b.x);
    q[4] = fpack2(b.x, b.y);
}

__global__ void __launch_bounds__(THREADS)
dwconv3x3_kernel(const float* __restrict__ x,
                 const float* __restrict__ w,
                 float* __restrict__ out) {
    __shared__ __align__(16) float sm[ROWS_IN * ROW_F];

    const int tile = blockIdx.x;   // 0..50
    const int c    = blockIdx.y;   // 0..63
    const int n    = blockIdx.z;   // 0..15

    const int tid  = threadIdx.x;
    const int wid  = tid >> 5;             // warp 0..3
    const int lane = tid & 31;
    const int x0   = tid * 4;              // first owned output column
    const bool last = (x0 == 508);         // thread 127: 2 valid outputs only

    const size_t img_off = ((size_t)(n * 64 + c)) * (512 * 512);
    const size_t out_off = ((size_t)(n * 64 + c)) * (510 * 510);
    const float* img = x + img_off;
    float* o = out + out_off;

    const int r0 = tile * TILE_H;          // first output row of this tile

    // Per-warp region write addresses.
    const uint32_t smBase = (uint32_t)__cvta_generic_to_shared(sm);
    const uint32_t wrBase = smBase + (uint32_t)((wid * WREG_F) * 4);
    const uint32_t laneWr = wrBase + (uint32_t)(lane * 16);
    const uint32_t haloWr = wrBase + 128 * 4;  // offset of halo pair

    // Halo source: first 2 floats of the next warp's 128-col span.
    // Warp 3's halo (cols 512/513) is consumed only by unstored outputs ->
    // load from a safe dummy (img base) instead of risking OOB.
    const bool haloReal = (wid < 3);
    const float* haloSrcBase = haloReal ? img + (wid + 1) * 128 : img;

    // Burst prefetch: one commit-group per row. Lane 31 adds the 8B halo.
#pragma unroll
    for (int rr = 0; rr < ROWS_IN; ++rr) {
        const size_t roff = (size_t)(r0 + rr) * 512;
        cp_async16(laneWr + rr * (ROW_F * 4), img + roff + x0);
        if (lane == 31) {
            cp_async8(haloWr + rr * (ROW_F * 4),
                      haloReal ? haloSrcBase + roff : haloSrcBase);
        }
        cp_commit();
    }

    // Broadcast weights as (w,w) f32x2 pairs.
    const float* wc = w + c * 9;
    u64 wp[9];
#pragma unroll
    for (int i = 0; i < 9; ++i) {
        float wv = __ldg(wc + i);
        wp[i] = fpack2(wv, wv);
    }

    // This lane's read pointer inside its warp region (floats).
    const float* laneRd = sm + wid * WREG_F + lane * 4;

    // Rolling 3-row window of overlapping pairs.
    u64 q[3][5];
    cp_wait<ROWS_IN - 2>();   // rows 0,1 retired (groups retire in order)
    __syncwarp();             // publish within the warp (warp-private data)
    pairs_from_region(laneRd + 0 * ROW_F, q[0]);
    pairs_from_region(laneRd + 1 * ROW_F, q[1]);

#pragma unroll
    for (int r = 0; r < TILE_H; ++r) {
        const int top = r % 3;
        const int mid = (r + 1) % 3;
        const int bot = (r + 2) % 3;

        cp_wait_rt(r);        // row r+2 landed (own groups)
        __syncwarp();         // warp-local publish; warps drift freely

        pairs_from_region(laneRd + (r + 2) * ROW_F, q[bot]);

        // outputs (x0, x0+1)
        u64 acc01 = fmul2(wp[0], q[top][0]);
        acc01 = ffma2(wp[1], q[top][1], acc01);
        acc01 = ffma2(wp[2], q[top][2], acc01);
        acc01 = ffma2(wp[3], q[mid][0], acc01);
        acc01 = ffma2(wp[4], q[mid][1], acc01);
        acc01 = ffma2(wp[5], q[mid][2], acc01);
        acc01 = ffma2(wp[6], q[bot][0], acc01);
        acc01 = ffma2(wp[7], q[bot][1], acc01);
        acc01 = ffma2(wp[8], q[bot][2], acc01);

        // outputs (x0+2, x0+3)
        u64 acc23 = fmul2(wp[0], q[top][2]);
        acc23 = ffma2(wp[1], q[top][3], acc23);
        acc23 = ffma2(wp[2], q[top][4], acc23);
        acc23 = ffma2(wp[3], q[mid][2], acc23);
        acc23 = ffma2(wp[4], q[mid][3], acc23);
        acc23 = ffma2(wp[5], q[mid][4], acc23);
        acc23 = ffma2(wp[6], q[bot][2], acc23);
        acc23 = ffma2(wp[7], q[bot][3], acc23);
        acc23 = ffma2(wp[8], q[bot][4], acc23);

        // Row stride 510*4 = 2040 B is 8-byte aligned -> STG.64 stores.
        float* orow = o + (size_t)(r0 + r) * 510 + x0;
        *reinterpret_cast<u64*>(orow) = acc01;
        if (!last) {
            *reinterpret_cast<u64*>(orow + 2) = acc23;
        }
    }
}

extern "C" void kernel_launch(void* const* d_in, const int* in_sizes, int n_in,
                              void* d_out, int out_size) {
    const float* x = (const float*)d_in[0];
    const float* w = (const float*)d_in[1];
    // Defensive: metadata order is (x, weight); swap if sizes say otherwise.
    if (n_in >= 2 && in_sizes[0] < in_sizes[1]) {
        const float* t = x; x = w; w = t;
    }
    float* out = (float*)d_out;

    dim3 grid(51, 64, 16); // 510/TILE_H row tiles, C, N
    dwconv3x3_kernel<<<grid, THREADS>>>(x, w, out);
}

// round 16
// speedup vs baseline: 1.0502x; 1.0466x over previous
#include <cuda_runtime.h>
#include <cstdint>

// Depthwise 3x3 conv, stride 1, VALID, C=64.
// x: (16, 64, 512, 512) f32, w: (64, 3, 3) f32 -> out: (16, 64, 510, 510) f32
//
// R15 = R8 byte-identical structure (burst 12-row cp.async prefetch, one
// commit group per row, per-row progressive wait_group + __syncthreads,
// rolling 3-row FFMA2 window, STG.64 -- best measured: 305us, DRAM=87.3%,
// occ=48%) + two pure cache-policy hints:
//   1. cp.async.cg.shared.global.L2::256B  -- larger L2/DRAM fetch granules
//      (all bytes wanted: rows are contiguous 2KB per block).
//   2. st.global.cs for outputs -- write-once data, evict-first; keeps L2
//      for input halo sharing and smooths the DRAM R/W interleave.
// No change to regs/smem/occupancy.

#define TILE_H 10    // 510 = 51 * 10
#define ROWS_IN (TILE_H + 2)
#define THREADS 128  // 128 threads * 4 cols = 512
#define SLOT_F 520   // floats per smem row slot (512 data + 2 zero + pad)

typedef unsigned long long u64;

__device__ __forceinline__ u64 fpack2(float lo, float hi) {
    u64 d;
    asm("mov.b64 %0, {%1, %2};" : "=l"(d) : "f"(lo), "f"(hi));
    return d;
}

__device__ __forceinline__ u64 fmul2(u64 a, u64 b) {
    u64 d;
    asm("mul.rn.f32x2 %0, %1, %2;" : "=l"(d) : "l"(a), "l"(b));
    return d;
}

__device__ __forceinline__ u64 ffma2(u64 a, u64 b, u64 c) {
    u64 d;
    asm("fma.rn.f32x2 %0, %1, %2, %3;" : "=l"(d) : "l"(a), "l"(b), "l"(c));
    return d;
}

__device__ __forceinline__ void cp_async16(uint32_t smem_addr,
                                           const float* gptr) {
    asm volatile("cp.async.cg.shared.global.L2::256B [%0], [%1], 16;"
                 :: "r"(smem_addr), "l"(gptr));
}

__device__ __forceinline__ void cp_commit() {
    asm volatile("cp.async.commit_group;");
}

template <int N>
__device__ __forceinline__ void cp_wait() {
    asm volatile("cp.async.wait_group %0;" :: "n"(N));
}

__device__ __forceinline__ void stcs64(float* p, u64 v) {
    asm volatile("st.global.cs.u64 [%0], %1;" :: "l"(p), "l"(v) : "memory");
}

// Progressive wait; r is compile-time in the unrolled loop, branches fold.
__device__ __forceinline__ void cp_wait_rt(int r) {
    if (r == 0) cp_wait<9>();
    else if (r == 1) cp_wait<8>();
    else if (r == 2) cp_wait<7>();
    else if (r == 3) cp_wait<6>();
    else if (r == 4) cp_wait<5>();
    else if (r == 5) cp_wait<4>();
    else if (r == 6) cp_wait<3>();
    else if (r == 7) cp_wait<2>();
    else if (r == 8) cp_wait<1>();
    else cp_wait<0>();
}

// Build 5 overlapping f32x2 pairs from a smem row slot (uniform; cols
// 512/513 hold zeros so thread 127 needs no branch).
__device__ __forceinline__ void pairs_from_smem(const float* srow, int x0,
                                                u64 q[5]) {
    float4 a = *reinterpret_cast<const float4*>(srow + x0);
    float2 b = *reinterpret_cast<const float2*>(srow + x0 + 4);
    q[0] = fpack2(a.x, a.y);
    q[1] = fpack2(a.y, a.z);
    q[2] = fpack2(a.z, a.w);
    q[3] = fpack2(a.w, b.x);
    q[4] = fpack2(b.x, b.y);
}

__global__ void __launch_bounds__(THREADS)
dwconv3x3_kernel(const float* __restrict__ x,
                 const float* __restrict__ w,
                 float* __restrict__ out) {
    __shared__ __align__(16) float sm[ROWS_IN * SLOT_F];

    const int tile = blockIdx.x;   // 0..50
    const int c    = blockIdx.y;   // 0..63
    const int n    = blockIdx.z;   // 0..15

    const int tid = threadIdx.x;
    const int x0  = tid * 4;               // first owned output column
    const bool last = (x0 == 508);         // thread 127: 2 valid outputs only

    const size_t img_off = ((size_t)(n * 64 + c)) * (512 * 512);
    const size_t out_off = ((size_t)(n * 64 + c)) * (510 * 510);
    const float* img = x + img_off;
    float* o = out + out_off;

    const int r0 = tile * TILE_H;          // first output row of this tile

    // Issue the whole tile's loads up front: one 16B cp.async per thread per
    // row, one commit-group per row. ~25KB in flight per block.
    const uint32_t smem_base =
        (uint32_t)__cvta_generic_to_shared(sm) + (uint32_t)(x0 * 4);
#pragma unroll
    for (int rr = 0; rr < ROWS_IN; ++rr) {
        cp_async16(smem_base + rr * (SLOT_F * 4),
                   img + (size_t)(r0 + rr) * 512 + x0);
        cp_commit();
    }

    // Zero the 2 halo floats of each slot (cols 512/513). Disjoint from the
    // cp.async target range, so no race.
    if (tid < ROWS_IN) {
        *reinterpret_cast<float2*>(sm + tid * SLOT_F + 512) =
            make_float2(0.0f, 0.0f);
    }

    // Broadcast weights as (w,w) f32x2 pairs.
    const float* wc = w + c * 9;
    u64 wp[9];
#pragma unroll
    for (int i = 0; i < 9; ++i) {
        float wv = __ldg(wc + i);
        wp[i] = fpack2(wv, wv);
    }

    // Rolling 3-row window of overlapping pairs.
    u64 q[3][5];
    cp_wait<ROWS_IN - 2>();   // rows 0,1 arrived (groups retire in order)
    __syncthreads();
    pairs_from_smem(sm + 0 * SLOT_F, x0, q[0]);
    pairs_from_smem(sm + 1 * SLOT_F, x0, q[1]);

#pragma unroll
    for (int r = 0; r < TILE_H; ++r) {
        const int top = r % 3;
        const int mid = (r + 1) % 3;
        const int bot = (r + 2) % 3;

        cp_wait_rt(r);        // row r+2 has landed
        __syncthreads();

        pairs_from_smem(sm + (r + 2) * SLOT_F, x0, q[bot]);

        // outputs (x0, x0+1)
        u64 acc01 = fmul2(wp[0], q[top][0]);
        acc01 = ffma2(wp[1], q[top][1], acc01);
        acc01 = ffma2(wp[2], q[top][2], acc01);
        acc01 = ffma2(wp[3], q[mid][0], acc01);
        acc01 = ffma2(wp[4], q[mid][1], acc01);
        acc01 = ffma2(wp[5], q[mid][2], acc01);
        acc01 = ffma2(wp[6], q[bot][0], acc01);
        acc01 = ffma2(wp[7], q[bot][1], acc01);
        acc01 = ffma2(wp[8], q[bot][2], acc01);

        // outputs (x0+2, x0+3)
        u64 acc23 = fmul2(wp[0], q[top][2]);
        acc23 = ffma2(wp[1], q[top][3], acc23);
        acc23 = ffma2(wp[2], q[top][4], acc23);
        acc23 = ffma2(wp[3], q[mid][2], acc23);
        acc23 = ffma2(wp[4], q[mid][3], acc23);
        acc23 = ffma2(wp[5], q[mid][4], acc23);
        acc23 = ffma2(wp[6], q[bot][2], acc23);
        acc23 = ffma2(wp[7], q[bot][3], acc23);
        acc23 = ffma2(wp[8], q[bot][4], acc23);

        // Row stride 510*4 = 2040 B is 8-byte aligned -> STG.64 stores.
        float* orow = o + (size_t)(r0 + r) * 510 + x0;
        stcs64(orow, acc01);
        if (!last) {
            stcs64(orow + 2, acc23);
        }
    }
}

extern "C" void kernel_launch(void* const* d_in, const int* in_sizes, int n_in,
                              void* d_out, int out_size) {
    const float* x = (const float*)d_in[0];
    const float* w = (const float*)d_in[1];
    // Defensive: metadata order is (x, weight); swap if sizes say otherwise.
    if (n_in >= 2 && in_sizes[0] < in_sizes[1]) {
        const float* t = x; x = w; w = t;
    }
    float* out = (float*)d_out;

    dim3 grid(51, 64, 16); // 510/TILE_H row tiles, C, N
    dwconv3x3_kernel<<<grid, THREADS>>>(x, w, out);
}